// round 17
// baseline (speedup 1.0000x reference)
#include <cuda_runtime.h>
#include <cuda_fp16.h>

// ---------------------------------------------------------------------------
// OpticalFlowLoss two-pass kernel (sm_103a)
// Pass 1: streaming RGB->fp16 gray (pred & gt) + fp16 motion-magnitude.
// Pass 2: Sobel/flow stencil on fp16 gray (L2-resident), global reduce.
// pred, gt: [B=8, T=8, C=3, H=256, W=256] fp32 -> scalar fp32 loss
// ---------------------------------------------------------------------------

#define B_    8
#define T_    8
#define H_    256
#define W_    256
#define HW_   (H_ * W_)          // 65536
#define FRAME_STRIDE (3 * HW_)
#define NFRAMES (B_ * T_)        // 64
#define NPAIRS (B_ * (T_ - 1))   // 56

#define TILE_W 64
#define TILE_H 32
#define HALO_H (TILE_H + 2)      // 34
#define SCOLS  72
#define SLOTS  (SCOLS / 4)       // 18

#define NBLOCKS2 ((W_ / TILE_W) * (H_ / TILE_H) * NPAIRS)  // 1792

#define EPSF 1e-3f
#define MEAN_COUNT 7340032.0     // 8*7*2*256*256

// fp16 scratch (static device arrays: allowed)
__device__ __half g_grayP[NFRAMES * HW_];   // 8.4 MB
__device__ __half g_grayG[NFRAMES * HW_];   // 8.4 MB
__device__ __half g_mm[NPAIRS * HW_];       // 7.3 MB

__device__ double g_accum;       // zero-init; self-resetting
__device__ unsigned int g_done;  // zero-init; self-resetting

__device__ __forceinline__ float gray3(float r, float g, float b) {
    return 0.2989f * r + 0.587f * g + 0.114f * b;
}

__device__ __forceinline__ void store4h(__half* base, int idx,
                                        float a, float b, float c, float d) {
    __half2 h0 = __floats2half2_rn(a, b);
    __half2 h1 = __floats2half2_rn(c, d);
    uint2 u;
    u.x = *(unsigned*)&h0;
    u.y = *(unsigned*)&h1;
    *(uint2*)(base + idx) = u;   // idx multiple of 4 -> 8B aligned
}

__device__ __forceinline__ float4 load4h(const __half* base, int idx) {
    uint2 u = __ldg((const uint2*)(base + idx));
    __half2 h0 = *(__half2*)&u.x;
    __half2 h1 = *(__half2*)&u.y;
    float2 f0 = __half22float2(h0);
    float2 f1 = __half22float2(h1);
    return make_float4(f0.x, f0.y, f1.x, f1.y);
}

// ---------------- Pass 1: gray + mm precompute (streaming) ----------------
__global__ __launch_bounds__(256)
void pass1_kernel(const float* __restrict__ pred,
                  const float* __restrict__ gt) {
    const int f  = blockIdx.y;                       // 0..63
    const int t  = f & 7;
    const int px = (blockIdx.x * 256 + threadIdx.x) * 4;
    const int base = f * FRAME_STRIDE + px;

    // pred gray
    float4 r = __ldg((const float4*)(pred + base));
    float4 g = __ldg((const float4*)(pred + base + HW_));
    float4 b = __ldg((const float4*)(pred + base + 2 * HW_));
    store4h(g_grayP, f * HW_ + px,
            gray3(r.x, g.x, b.x), gray3(r.y, g.y, b.y),
            gray3(r.z, g.z, b.z), gray3(r.w, g.w, b.w));

    // gt gray (keep RGB for mm)
    float4 rg = __ldg((const float4*)(gt + base));
    float4 gg = __ldg((const float4*)(gt + base + HW_));
    float4 bg = __ldg((const float4*)(gt + base + 2 * HW_));
    store4h(g_grayG, f * HW_ + px,
            gray3(rg.x, gg.x, bg.x), gray3(rg.y, gg.y, bg.y),
            gray3(rg.z, gg.z, bg.z), gray3(rg.w, gg.w, bg.w));

    // motion magnitude for pair (b, t), t < 7
    if (t < 7) {
        float4 rn = __ldg((const float4*)(gt + base + FRAME_STRIDE));
        float4 gn = __ldg((const float4*)(gt + base + FRAME_STRIDE + HW_));
        float4 bn = __ldg((const float4*)(gt + base + FRAME_STRIDE + 2 * HW_));
        const float k = 1.0f / 3.0f;
        float m0 = (fabsf(rn.x - rg.x) + fabsf(gn.x - gg.x) + fabsf(bn.x - bg.x)) * k;
        float m1 = (fabsf(rn.y - rg.y) + fabsf(gn.y - gg.y) + fabsf(bn.y - bg.y)) * k;
        float m2 = (fabsf(rn.z - rg.z) + fabsf(gn.z - gg.z) + fabsf(bn.z - bg.z)) * k;
        float m3 = (fabsf(rn.w - rg.w) + fabsf(gn.w - gg.w) + fabsf(bn.w - bg.w)) * k;
        store4h(g_mm, ((f >> 3) * 7 + t) * HW_ + px, m0, m1, m2, m3);
    }
}

// ---------------- Pass 2: Sobel / flow stencil + reduction ----------------
__global__ __launch_bounds__(256)
void pass2_kernel(float* __restrict__ out) {
    const int pair = blockIdx.z;          // 0..55
    const int b = pair / (T_ - 1);
    const int t = pair % (T_ - 1);
    const int f1 = b * T_ + t;
    const int f2 = f1 + 1;

    const int tileX = blockIdx.x * TILE_W;
    const int tileY = blockIdx.y * TILE_H;

    __shared__ float sP[HALO_H][SCOLS];
    __shared__ float sG[HALO_H][SCOLS];

    // --- halo fill from fp16 gray (one 8B load per image per slot) ---
    for (int i = threadIdx.x; i < HALO_H * SLOTS; i += 256) {
        int hy = i / SLOTS;
        int sl = i - hy * SLOTS;
        int gh = tileY + hy - 1;
        int gc = tileX - 4 + sl * 4;
        float4 vp = make_float4(0.f, 0.f, 0.f, 0.f);
        float4 vg = vp;
        if ((unsigned)gh < H_ && (unsigned)gc < W_) {
            int idx = gh * W_ + gc;
            vp = load4h(g_grayP, f1 * HW_ + idx);
            vg = load4h(g_grayG, f1 * HW_ + idx);
        }
        *(float4*)&sP[hy][sl * 4] = vp;
        *(float4*)&sG[hy][sl * 4] = vg;
    }
    __syncthreads();

    float acc = 0.0f;

    #pragma unroll
    for (int k = 0; k < 2; ++k) {
        int i  = threadIdx.x + k * 256;
        int ly = i >> 4;            // 0..31
        int sx = (i & 15) * 4;      // 0..60
        int off = (tileY + ly) * W_ + tileX + sx;

        float4 gyP2 = load4h(g_grayP, f2 * HW_ + off);
        float4 gyG2 = load4h(g_grayG, f2 * HW_ + off);
        float4 mm4  = load4h(g_mm,   pair * HW_ + off);
        float gp2[4] = {gyP2.x, gyP2.y, gyP2.z, gyP2.w};
        float gg2[4] = {gyG2.x, gyG2.y, gyG2.z, gyG2.w};
        float mmv[4] = {mm4.x, mm4.y, mm4.z, mm4.w};

        // pred Sobel + flow
        float uP[4], vP[4];
        {
            float4 a0 = *(const float4*)&sP[ly    ][sx];
            float4 m0 = *(const float4*)&sP[ly    ][sx + 4];
            float  c0 = sP[ly    ][sx + 8];
            float4 a1 = *(const float4*)&sP[ly + 1][sx];
            float4 m1 = *(const float4*)&sP[ly + 1][sx + 4];
            float  c1 = sP[ly + 1][sx + 8];
            float4 a2 = *(const float4*)&sP[ly + 2][sx];
            float4 m2 = *(const float4*)&sP[ly + 2][sx + 4];
            float  c2 = sP[ly + 2][sx + 8];
            float t0[6] = {a0.w, m0.x, m0.y, m0.z, m0.w, c0};
            float t1[6] = {a1.w, m1.x, m1.y, m1.z, m1.w, c1};
            float t2[6] = {a2.w, m2.x, m2.y, m2.z, m2.w, c2};
            #pragma unroll
            for (int p = 0; p < 4; ++p) {
                float Ix = (t0[p] - t0[p + 2]) + 2.0f * (t1[p] - t1[p + 2])
                         + (t2[p] - t2[p + 2]);
                float Iy = (t0[p] + 2.0f * t0[p + 1] + t0[p + 2])
                         - (t2[p] + 2.0f * t2[p + 1] + t2[p + 2]);
                float It = gp2[p] - t1[p + 1];
                float inv = __fdividef(1.0f, Ix * Ix + Iy * Iy + EPSF);
                uP[p] = -Ix * It * inv;
                vP[p] = -Iy * It * inv;
            }
        }

        // gt Sobel + flow + accumulate
        {
            float4 a0 = *(const float4*)&sG[ly    ][sx];
            float4 m0 = *(const float4*)&sG[ly    ][sx + 4];
            float  c0 = sG[ly    ][sx + 8];
            float4 a1 = *(const float4*)&sG[ly + 1][sx];
            float4 m1 = *(const float4*)&sG[ly + 1][sx + 4];
            float  c1 = sG[ly + 1][sx + 8];
            float4 a2 = *(const float4*)&sG[ly + 2][sx];
            float4 m2 = *(const float4*)&sG[ly + 2][sx + 4];
            float  c2 = sG[ly + 2][sx + 8];
            float t0[6] = {a0.w, m0.x, m0.y, m0.z, m0.w, c0};
            float t1[6] = {a1.w, m1.x, m1.y, m1.z, m1.w, c1};
            float t2[6] = {a2.w, m2.x, m2.y, m2.z, m2.w, c2};
            #pragma unroll
            for (int p = 0; p < 4; ++p) {
                float Ix = (t0[p] - t0[p + 2]) + 2.0f * (t1[p] - t1[p + 2])
                         + (t2[p] - t2[p + 2]);
                float Iy = (t0[p] + 2.0f * t0[p + 1] + t0[p + 2])
                         - (t2[p] + 2.0f * t2[p + 1] + t2[p + 2]);
                float It = gg2[p] - t1[p + 1];
                float inv = __fdividef(1.0f, Ix * Ix + Iy * Iy + EPSF);
                float uG = -Ix * It * inv;
                float vG = -Iy * It * inv;
                acc += (fabsf(uP[p] - uG) + fabsf(vP[p] - vG)) * mmv[p];
            }
        }
    }

    // --- block reduction ---
    #pragma unroll
    for (int s = 16; s > 0; s >>= 1)
        acc += __shfl_xor_sync(0xFFFFFFFFu, acc, s);

    __shared__ float warpSum[8];
    int lane = threadIdx.x & 31;
    int wid  = threadIdx.x >> 5;
    if (lane == 0) warpSum[wid] = acc;
    __syncthreads();

    if (wid == 0 && lane == 0) {
        float v = 0.0f;
        #pragma unroll
        for (int j = 0; j < 8; ++j) v += warpSum[j];
        atomicAdd(&g_accum, (double)v);
        __threadfence();
        unsigned ticket = atomicAdd(&g_done, 1u);
        if (ticket == NBLOCKS2 - 1) {
            out[0] = (float)(g_accum / MEAN_COUNT);
            g_accum = 0.0;
            __threadfence();
            g_done = 0u;
        }
    }
}

extern "C" void kernel_launch(void* const* d_in, const int* in_sizes, int n_in,
                              void* d_out, int out_size) {
    const float* pred = (const float*)d_in[0];
    const float* gt   = (const float*)d_in[1];
    float* out = (float*)d_out;

    dim3 g1(HW_ / (256 * 4), NFRAMES);            // (64, 64)
    pass1_kernel<<<g1, 256>>>(pred, gt);

    dim3 g2(W_ / TILE_W, H_ / TILE_H, NPAIRS);    // (4, 8, 56)
    pass2_kernel<<<g2, 256>>>(out);
}